// round 2
// baseline (speedup 1.0000x reference)
#include <cuda_runtime.h>
#include <cstdint>

#define BATCH 8
#define NN 2048
#define FF 128

// ---------------- scratch (static device globals; no allocation) ----------------
__device__ float g_h[BATCH * NN * FF];                 // h, then h/D (tf32-rounded) in place
__device__ float g_s1[BATCH * NN], g_s2p[BATCH * NN];  // s1, s2 + b_a
__device__ float g_u1[BATCH * NN], g_u2[BATCH * NN];   // exp(s1), exp(s2p)
__device__ float g_v1[BATCH * NN], g_v2[BATCH * NN];   // exp(0.2 s1), exp(0.2 s2p)
__device__ float g_D[BATCH * NN], g_invD[BATCH * NN];

__device__ __forceinline__ unsigned f2tf32(float f) {
    unsigned u;
    asm("cvt.rna.tf32.f32 %0, %1;" : "=r"(u) : "f"(f));
    return u;
}

__device__ __forceinline__ void mma_tf32(float* d, const unsigned* a, const unsigned* b) {
    asm volatile(
        "mma.sync.aligned.m16n8k8.row.col.f32.tf32.tf32.f32 "
        "{%0,%1,%2,%3}, {%4,%5,%6,%7}, {%8,%9}, {%0,%1,%2,%3};\n"
        : "+f"(d[0]), "+f"(d[1]), "+f"(d[2]), "+f"(d[3])
        : "r"(a[0]), "r"(a[1]), "r"(a[2]), "r"(a[3]), "r"(b[0]), "r"(b[1]));
}

// ---------------- kernel 1: h = x @ W + b_W  (M=16384, K=128, N=128) ----------------
__global__ __launch_bounds__(256) void k_gemm_h(const float* __restrict__ x,
                                                const float* __restrict__ W,
                                                const float* __restrict__ bW) {
    __shared__ float XsT[32][68];   // [k][m] transposed, padded
    __shared__ float Ws[32][128];   // [k][n]
    const int t = threadIdx.x;
    const int tx = t & 15, ty = t >> 4;
    const int m0 = blockIdx.x * 64;

    float acc[4][8];
#pragma unroll
    for (int i = 0; i < 4; i++)
#pragma unroll
        for (int j = 0; j < 8; j++) acc[i][j] = 0.f;

    for (int k0 = 0; k0 < 128; k0 += 32) {
#pragma unroll
        for (int it = 0; it < 2; it++) {
            int q = t + it * 256;
            int rr = q >> 3, c4 = q & 7;
            float4 v = *(const float4*)&x[(m0 + rr) * 128 + k0 + c4 * 4];
            XsT[c4 * 4 + 0][rr] = v.x;
            XsT[c4 * 4 + 1][rr] = v.y;
            XsT[c4 * 4 + 2][rr] = v.z;
            XsT[c4 * 4 + 3][rr] = v.w;
        }
#pragma unroll
        for (int it = 0; it < 4; it++) {
            int q = t + it * 256;
            int rr = q >> 5, c4 = q & 31;
            *(float4*)&Ws[rr][c4 * 4] = *(const float4*)&W[(k0 + rr) * 128 + c4 * 4];
        }
        __syncthreads();
#pragma unroll
        for (int kk = 0; kk < 32; kk++) {
            float4 a = *(float4*)&XsT[kk][ty * 4];
            float4 b0 = *(float4*)&Ws[kk][tx * 4];
            float4 b1 = *(float4*)&Ws[kk][64 + tx * 4];
            float aa[4] = {a.x, a.y, a.z, a.w};
            float bb[8] = {b0.x, b0.y, b0.z, b0.w, b1.x, b1.y, b1.z, b1.w};
#pragma unroll
            for (int i = 0; i < 4; i++)
#pragma unroll
                for (int j = 0; j < 8; j++) acc[i][j] = fmaf(aa[i], bb[j], acc[i][j]);
        }
        __syncthreads();
    }

    float4 bwA = *(const float4*)&bW[tx * 4];
    float4 bwB = *(const float4*)&bW[64 + tx * 4];
#pragma unroll
    for (int i = 0; i < 4; i++) {
        int row = m0 + ty * 4 + i;
        float4 o0 = {acc[i][0] + bwA.x, acc[i][1] + bwA.y, acc[i][2] + bwA.z, acc[i][3] + bwA.w};
        float4 o1 = {acc[i][4] + bwB.x, acc[i][5] + bwB.y, acc[i][6] + bwB.z, acc[i][7] + bwB.w};
        *(float4*)&g_h[row * 128 + tx * 4] = o0;
        *(float4*)&g_h[row * 128 + 64 + tx * 4] = o1;
    }
}

// ---------------- kernel 2: per-node stats s1,s2',u,v ----------------
__global__ __launch_bounds__(128) void k_rowstats(const float* __restrict__ a1,
                                                  const float* __restrict__ a2,
                                                  const float* __restrict__ ba) {
    const int row = blockIdx.x;
    const int t = threadIdx.x;
    float hv = g_h[row * 128 + t];
    float p1 = hv * a1[t];
    float p2 = hv * a2[t];
#pragma unroll
    for (int off = 16; off > 0; off >>= 1) {
        p1 += __shfl_down_sync(0xffffffffu, p1, off);
        p2 += __shfl_down_sync(0xffffffffu, p2, off);
    }
    __shared__ float r1[4], r2[4];
    if ((t & 31) == 0) { r1[t >> 5] = p1; r2[t >> 5] = p2; }
    __syncthreads();
    if (t == 0) {
        float s1v = r1[0] + r1[1] + r1[2] + r1[3];
        float s2v = r2[0] + r2[1] + r2[2] + r2[3];
        float s2pv = s2v + ba[0];
        g_s1[row] = s1v;
        g_s2p[row] = s2pv;
        g_u1[row] = expf(s1v);
        g_u2[row] = expf(s2pv);
        g_v1[row] = expf(0.2f * s1v);
        g_v2[row] = expf(0.2f * s2pv);
    }
}

// ---------------- kernel 3a: zero D ----------------
__global__ void k_zeroD() {
    int i = blockIdx.x * 256 + threadIdx.x;
    if (i < BATCH * NN) g_D[i] = 0.f;
}

// ---------------- kernel 3b: column sums D[b,j] = sum_i masked exp ----------------
// grid (2, 16, 8): x = 1024-col block, y = 128-row chunk, z = batch. 256 thr, 4 cols/thread.
__global__ __launch_bounds__(256) void k_colsum(const int* __restrict__ adj) {
    const int t = threadIdx.x;
    const int jb = blockIdx.x, ic = blockIdx.y, b = blockIdx.z;
    const int i0 = ic * 128;
    const int nb = b * NN;
    __shared__ float s1s[128], u1s[128], v1s[128];
    if (t < 128) {
        s1s[t] = g_s1[nb + i0 + t];
        u1s[t] = g_u1[nb + i0 + t];
        v1s[t] = g_v1[nb + i0 + t];
    }
    __syncthreads();

    const int jloc = jb * 1024 + t * 4;
    float s2p[4], u2[4], v2[4], accU[4], accV[4];
#pragma unroll
    for (int q = 0; q < 4; q++) {
        s2p[q] = g_s2p[nb + jloc + q];
        u2[q] = g_u2[nb + jloc + q];
        v2[q] = g_v2[nb + jloc + q];
        accU[q] = 0.f;
        accV[q] = 0.f;
    }
    const int4* arow = (const int4*)(adj + (size_t)b * NN * NN + (size_t)i0 * NN + jb * 1024);
    const int stride4 = NN / 4;
    for (int ii = 0; ii < 128; ii++) {
        int4 av = arow[ii * stride4 + t];
        float s1i = s1s[ii], u1i = u1s[ii], v1i = v1s[ii];
        int e[4] = {av.x, av.y, av.z, av.w};
#pragma unroll
        for (int q = 0; q < 4; q++) {
            float tt = s1i + s2p[q];
            bool m = e[q] > 0;
            accU[q] += (m && tt > 0.f) ? u1i : 0.f;
            accV[q] += (m && tt <= 0.f) ? v1i : 0.f;
        }
    }
#pragma unroll
    for (int q = 0; q < 4; q++) {
        float d = u2[q] * accU[q] + v2[q] * accV[q];
        atomicAdd(&g_D[nb + jloc + q], d);
    }
}

// ---------------- kernel 3c: invD (guard fully-masked columns -> 0, avoids 0*inf NaN) ----------------
__global__ void k_finalizeD() {
    int i = blockIdx.x * 256 + threadIdx.x;
    if (i < BATCH * NN) {
        float d = g_D[i];
        g_invD[i] = (d != 0.f) ? (1.f / d) : 0.f;
    }
}

// ---------------- kernel 4: h2 = h / D[row], tf32-rounded, in place ----------------
__global__ __launch_bounds__(256) void k_scaleH() {
    int idx = blockIdx.x * 256 + threadIdx.x;  // float4 index, 524288 total
    float4* hp = (float4*)g_h;
    float4 v = hp[idx];
    float inv = g_invD[idx >> 5];
    v.x = __uint_as_float(f2tf32(v.x * inv));
    v.y = __uint_as_float(f2tf32(v.y * inv));
    v.z = __uint_as_float(f2tf32(v.z * inv));
    v.w = __uint_as_float(f2tf32(v.w * inv));
    hp[idx] = v;
}

// ---------------- kernel 5: out = relu(P @ h2), P built on the fly ----------------
// grid (16, 8): x = 128-row i-block, y = batch. 256 thr = 8 warps, warp grid 4(M) x 2(N).
__device__ __forceinline__ unsigned pfrag(int e, float s1, float u1, float v1,
                                          float s2, float u2, float v2) {
    float tt = s1 + s2;
    float p = (tt > 0.f) ? (u1 * u2) : (v1 * v2);
    p = (e > 0) ? p : 0.f;
    return f2tf32(p);
}

__global__ __launch_bounds__(256, 1) void k_attn(const int* __restrict__ adj,
                                                 float* __restrict__ out) {
    __shared__ float s2sh[NN], u2sh[NN], v2sh[NN];
    __shared__ float Hs[32][136];

    const int b = blockIdx.y;
    const int i0 = blockIdx.x * 128;
    const int t = threadIdx.x;
    const int lane = t & 31, wid = t >> 5;
    const int wm = wid & 3, wn = wid >> 2;
    const int r = lane >> 2, c = lane & 3;
    const int nb = b * NN;

    for (int q = t; q < NN; q += 256) {
        s2sh[q] = g_s2p[nb + q];
        u2sh[q] = g_u2[nb + q];
        v2sh[q] = g_v2[nb + q];
    }

    int i_r[4];
    float s1v[4], u1v[4], v1v[4];
#pragma unroll
    for (int k = 0; k < 4; k++) {
        i_r[k] = i0 + wm * 32 + k * 8 + r;
        s1v[k] = g_s1[nb + i_r[k]];
        u1v[k] = g_u1[nb + i_r[k]];
        v1v[k] = g_v1[nb + i_r[k]];
    }
    const int* adjB = adj + (size_t)b * NN * NN;

    float acc[2][8][4];
#pragma unroll
    for (int mt = 0; mt < 2; mt++)
#pragma unroll
        for (int nt = 0; nt < 8; nt++)
#pragma unroll
            for (int q = 0; q < 4; q++) acc[mt][nt][q] = 0.f;

    for (int k0 = 0; k0 < NN; k0 += 32) {
#pragma unroll
        for (int it = 0; it < 4; it++) {
            int q = t + it * 256;
            int rr = q >> 5, cc = (q & 31) * 4;
            *(float4*)&Hs[rr][cc] = *(const float4*)&g_h[(size_t)(nb + k0 + rr) * FF + cc];
        }
        __syncthreads();
#pragma unroll
        for (int ks = 0; ks < 4; ks++) {
            const int jc = k0 + ks * 8 + c;
            const float s2a = s2sh[jc], u2a = u2sh[jc], v2a = v2sh[jc];
            const float s2b = s2sh[jc + 4], u2b = u2sh[jc + 4], v2b = v2sh[jc + 4];

            unsigned afr[2][4];
#pragma unroll
            for (int mt = 0; mt < 2; mt++) {
                const int rA = i_r[2 * mt], rB = i_r[2 * mt + 1];
                int e00 = adjB[rA * NN + jc];
                int e10 = adjB[rB * NN + jc];
                int e01 = adjB[rA * NN + jc + 4];
                int e11 = adjB[rB * NN + jc + 4];
                afr[mt][0] = pfrag(e00, s1v[2 * mt], u1v[2 * mt], v1v[2 * mt], s2a, u2a, v2a);
                afr[mt][1] = pfrag(e10, s1v[2 * mt + 1], u1v[2 * mt + 1], v1v[2 * mt + 1], s2a, u2a, v2a);
                afr[mt][2] = pfrag(e01, s1v[2 * mt], u1v[2 * mt], v1v[2 * mt], s2b, u2b, v2b);
                afr[mt][3] = pfrag(e11, s1v[2 * mt + 1], u1v[2 * mt + 1], v1v[2 * mt + 1], s2b, u2b, v2b);
            }
            unsigned bfr[8][2];
#pragma unroll
            for (int nt = 0; nt < 8; nt++) {
                int col = wn * 64 + nt * 8 + r;
                bfr[nt][0] = __float_as_uint(Hs[ks * 8 + c][col]);
                bfr[nt][1] = __float_as_uint(Hs[ks * 8 + c + 4][col]);
            }
#pragma unroll
            for (int mt = 0; mt < 2; mt++)
#pragma unroll
                for (int nt = 0; nt < 8; nt++) mma_tf32(acc[mt][nt], afr[mt], bfr[nt]);
        }
        __syncthreads();
    }

#pragma unroll
    for (int mt = 0; mt < 2; mt++) {
        const int rA = i_r[2 * mt], rB = i_r[2 * mt + 1];
#pragma unroll
        for (int nt = 0; nt < 8; nt++) {
            int col = wn * 64 + nt * 8 + 2 * c;
            float2 o0 = {fmaxf(acc[mt][nt][0], 0.f), fmaxf(acc[mt][nt][1], 0.f)};
            float2 o1 = {fmaxf(acc[mt][nt][2], 0.f), fmaxf(acc[mt][nt][3], 0.f)};
            *(float2*)&out[(size_t)(nb + rA) * FF + col] = o0;
            *(float2*)&out[(size_t)(nb + rB) * FF + col] = o1;
        }
    }
}

// ---------------- launch ----------------
extern "C" void kernel_launch(void* const* d_in, const int* in_sizes, int n_in,
                              void* d_out, int out_size) {
    const float* x = (const float*)d_in[0];
    const int* adj = (const int*)d_in[1];
    const float* W = (const float*)d_in[2];
    const float* bW = (const float*)d_in[3];
    const float* a1 = (const float*)d_in[4];
    const float* a2 = (const float*)d_in[5];
    const float* ba = (const float*)d_in[6];
    float* out = (float*)d_out;

    k_gemm_h<<<256, 256>>>(x, W, bW);
    k_rowstats<<<BATCH * NN, 128>>>(a1, a2, ba);
    k_zeroD<<<(BATCH * NN + 255) / 256, 256>>>();
    k_colsum<<<dim3(2, 16, 8), 256>>>(adj);
    k_finalizeD<<<(BATCH * NN + 255) / 256, 256>>>();
    k_scaleH<<<(BATCH * NN * FF / 4) / 256, 256>>>();
    k_attn<<<dim3(16, 8), 256>>>(adj, out);
}

// round 3
// speedup vs baseline: 1.4722x; 1.4722x over previous
#include <cuda_runtime.h>
#include <cstdint>

#define BATCH 8
#define NN 2048
#define FF 128

// ---------------- scratch (static device globals; no allocation) ----------------
__device__ float g_h[BATCH * NN * FF];                 // h (fp32)
__device__ float g_s1[BATCH * NN], g_s2p[BATCH * NN];  // s1, s2 + b_a
__device__ float g_u1[BATCH * NN], g_u2[BATCH * NN];   // exp(s1), exp(s2p)
__device__ float g_v1[BATCH * NN], g_v2[BATCH * NN];   // exp(0.2 s1), exp(0.2 s2p)
__device__ float g_DU[BATCH * NN], g_DV[BATCH * NN];   // column partial sums
__device__ float g_invD[BATCH * NN];
__device__ unsigned g_mask[BATCH * NN * (NN / 32)];    // adjacency bitmask [b][i][w]

__device__ __forceinline__ unsigned f2tf32(float f) {
    unsigned u;
    asm("cvt.rna.tf32.f32 %0, %1;" : "=r"(u) : "f"(f));
    return u;
}

__device__ __forceinline__ void mma_tf32(float* d, const unsigned* a, const unsigned* b) {
    asm volatile(
        "mma.sync.aligned.m16n8k8.row.col.f32.tf32.tf32.f32 "
        "{%0,%1,%2,%3}, {%4,%5,%6,%7}, {%8,%9}, {%0,%1,%2,%3};\n"
        : "+f"(d[0]), "+f"(d[1]), "+f"(d[2]), "+f"(d[3])
        : "r"(a[0]), "r"(a[1]), "r"(a[2]), "r"(a[3]), "r"(b[0]), "r"(b[1]));
}

// ---------------- kernel 1: h = x @ W + b_W, fused per-row stats ----------------
__global__ __launch_bounds__(256) void k_gemm_h(const float* __restrict__ x,
                                                const float* __restrict__ W,
                                                const float* __restrict__ bW,
                                                const float* __restrict__ a1,
                                                const float* __restrict__ a2,
                                                const float* __restrict__ ba) {
    __shared__ float XsT[32][68];   // [k][m] transposed, padded
    __shared__ float Ws[32][128];   // [k][n]
    const int t = threadIdx.x;
    const int tx = t & 15, ty = t >> 4;
    const int m0 = blockIdx.x * 64;

    float acc[4][8];
#pragma unroll
    for (int i = 0; i < 4; i++)
#pragma unroll
        for (int j = 0; j < 8; j++) acc[i][j] = 0.f;

    for (int k0 = 0; k0 < 128; k0 += 32) {
#pragma unroll
        for (int it = 0; it < 2; it++) {
            int q = t + it * 256;
            int rr = q >> 3, c4 = q & 7;
            float4 v = *(const float4*)&x[(m0 + rr) * 128 + k0 + c4 * 4];
            XsT[c4 * 4 + 0][rr] = v.x;
            XsT[c4 * 4 + 1][rr] = v.y;
            XsT[c4 * 4 + 2][rr] = v.z;
            XsT[c4 * 4 + 3][rr] = v.w;
        }
#pragma unroll
        for (int it = 0; it < 4; it++) {
            int q = t + it * 256;
            int rr = q >> 5, c4 = q & 31;
            *(float4*)&Ws[rr][c4 * 4] = *(const float4*)&W[(k0 + rr) * 128 + c4 * 4];
        }
        __syncthreads();
#pragma unroll
        for (int kk = 0; kk < 32; kk++) {
            float4 a = *(float4*)&XsT[kk][ty * 4];
            float4 b0 = *(float4*)&Ws[kk][tx * 4];
            float4 b1 = *(float4*)&Ws[kk][64 + tx * 4];
            float aa[4] = {a.x, a.y, a.z, a.w};
            float bb[8] = {b0.x, b0.y, b0.z, b0.w, b1.x, b1.y, b1.z, b1.w};
#pragma unroll
            for (int i = 0; i < 4; i++)
#pragma unroll
                for (int j = 0; j < 8; j++) acc[i][j] = fmaf(aa[i], bb[j], acc[i][j]);
        }
        __syncthreads();
    }

    float4 bwA = *(const float4*)&bW[tx * 4];
    float4 bwB = *(const float4*)&bW[64 + tx * 4];
    float4 a1A = *(const float4*)&a1[tx * 4];
    float4 a1B = *(const float4*)&a1[64 + tx * 4];
    float4 a2A = *(const float4*)&a2[tx * 4];
    float4 a2B = *(const float4*)&a2[64 + tx * 4];

    float p1[4], p2[4];
#pragma unroll
    for (int i = 0; i < 4; i++) {
        int row = m0 + ty * 4 + i;
        float4 o0 = {acc[i][0] + bwA.x, acc[i][1] + bwA.y, acc[i][2] + bwA.z, acc[i][3] + bwA.w};
        float4 o1 = {acc[i][4] + bwB.x, acc[i][5] + bwB.y, acc[i][6] + bwB.z, acc[i][7] + bwB.w};
        *(float4*)&g_h[row * 128 + tx * 4] = o0;
        *(float4*)&g_h[row * 128 + 64 + tx * 4] = o1;
        p1[i] = o0.x * a1A.x + o0.y * a1A.y + o0.z * a1A.z + o0.w * a1A.w +
                o1.x * a1B.x + o1.y * a1B.y + o1.z * a1B.z + o1.w * a1B.w;
        p2[i] = o0.x * a2A.x + o0.y * a2A.y + o0.z * a2A.z + o0.w * a2A.w +
                o1.x * a2B.x + o1.y * a2B.y + o1.z * a2B.z + o1.w * a2B.w;
    }
    // reduce across the 16 tx threads (half-warp: lanes 0-15 share ty, 16-31 share ty+1)
#pragma unroll
    for (int off = 8; off > 0; off >>= 1) {
#pragma unroll
        for (int i = 0; i < 4; i++) {
            p1[i] += __shfl_down_sync(0xffffffffu, p1[i], off);
            p2[i] += __shfl_down_sync(0xffffffffu, p2[i], off);
        }
    }
    if (tx == 0) {
        float ba0 = ba[0];
#pragma unroll
        for (int i = 0; i < 4; i++) {
            int row = m0 + ty * 4 + i;
            float s1v = p1[i];
            float s2pv = p2[i] + ba0;
            g_s1[row] = s1v;
            g_s2p[row] = s2pv;
            g_u1[row] = expf(s1v);
            g_u2[row] = expf(s2pv);
            g_v1[row] = expf(0.2f * s1v);
            g_v2[row] = expf(0.2f * s2pv);
        }
    }
}

// ---------------- kernel 2a: zero DU/DV ----------------
__global__ void k_zeroD() {
    int i = blockIdx.x * 256 + threadIdx.x;
    if (i < BATCH * NN) {
        g_DU[i] = 0.f;
        g_DV[i] = 0.f;
    }
}

// ---------------- kernel 2b: fused adj pack (bitmask) + column sums ----------------
// grid (2, 32, 8): x = 1024-col block, y = 64-row chunk, z = batch. 256 thr, 4 cols/thread.
__global__ __launch_bounds__(256) void k_pack(const int* __restrict__ adj) {
    const int t = threadIdx.x;
    const int jb = blockIdx.x, ic = blockIdx.y, b = blockIdx.z;
    const int i0 = ic * 64;
    const int nb = b * NN;
    __shared__ float s1s[64], u1s[64], v1s[64];
    if (t < 64) {
        s1s[t] = g_s1[nb + i0 + t];
        u1s[t] = g_u1[nb + i0 + t];
        v1s[t] = g_v1[nb + i0 + t];
    }
    __syncthreads();

    const int jloc = jb * 1024 + t * 4;
    const int sub = t & 7;
    float s2p[4], accU[4], accV[4];
#pragma unroll
    for (int q = 0; q < 4; q++) {
        s2p[q] = g_s2p[nb + jloc + q];
        accU[q] = 0.f;
        accV[q] = 0.f;
    }
    const int4* arow = (const int4*)(adj + (size_t)b * NN * NN + (size_t)i0 * NN + jb * 1024);
    unsigned* mrow = g_mask + (size_t)(nb + i0) * 64 + jb * 32 + (t >> 3);
    const int stride4 = NN / 4;

#pragma unroll 2
    for (int ii = 0; ii < 64; ii++) {
        int4 av = arow[ii * stride4 + t];
        bool m0 = av.x > 0, m1 = av.y > 0, m2 = av.z > 0, m3 = av.w > 0;
        unsigned nib = (m0 ? 1u : 0u) | (m1 ? 2u : 0u) | (m2 ? 4u : 0u) | (m3 ? 8u : 0u);
        unsigned w = nib << (sub * 4);
        w |= __shfl_xor_sync(0xffffffffu, w, 1);
        w |= __shfl_xor_sync(0xffffffffu, w, 2);
        w |= __shfl_xor_sync(0xffffffffu, w, 4);
        if (sub == 0) mrow[(size_t)ii * 64] = w;

        float s1i = s1s[ii], u1i = u1s[ii], v1i = v1s[ii];
        bool mm[4] = {m0, m1, m2, m3};
#pragma unroll
        for (int q = 0; q < 4; q++) {
            float tt = s1i + s2p[q];
            accU[q] += (mm[q] && tt > 0.f) ? u1i : 0.f;
            accV[q] += (mm[q] && tt <= 0.f) ? v1i : 0.f;
        }
    }
#pragma unroll
    for (int q = 0; q < 4; q++) {
        atomicAdd(&g_DU[nb + jloc + q], accU[q]);
        atomicAdd(&g_DV[nb + jloc + q], accV[q]);
    }
}

// ---------------- kernel 2c: invD = 1 / (u2*DU + v2*DV), 0-guarded ----------------
__global__ void k_finalizeD() {
    int i = blockIdx.x * 256 + threadIdx.x;
    if (i < BATCH * NN) {
        float d = g_u2[i] * g_DU[i] + g_v2[i] * g_DV[i];
        g_invD[i] = (d != 0.f) ? (1.f / d) : 0.f;
    }
}

// ---------------- kernel 3: out = relu(P @ (h*invD)), P built from bitmask ----------------
// grid (16, 8): x = 128-row i-block, y = batch. 256 thr = 8 warps, warp grid 4(M) x 2(N).
__device__ __forceinline__ unsigned pfrag(unsigned bit, float s1, float u1, float v1,
                                          float s2, float u2, float v2) {
    float tt = s1 + s2;
    float p = (tt > 0.f) ? (u1 * u2) : (v1 * v2);
    p = bit ? p : 0.f;
    return f2tf32(p);
}

__global__ __launch_bounds__(256, 1) void k_attn(float* __restrict__ out) {
    extern __shared__ float sm[];
    float* s2sh = sm;                 // [2048]
    float* u2sh = sm + 2048;          // [2048]
    float* v2sh = sm + 4096;          // [2048]
    float* invDsh = sm + 6144;        // [2048]
    float(*Hs)[136] = (float(*)[136])(sm + 8192);                   // 32*136
    unsigned(*Msk)[65] = (unsigned(*)[65])(sm + 8192 + 32 * 136);   // 128*65

    const int b = blockIdx.y;
    const int i0 = blockIdx.x * 128;
    const int t = threadIdx.x;
    const int lane = t & 31, wid = t >> 5;
    const int wm = wid & 3, wn = wid >> 2;
    const int r = lane >> 2, c = lane & 3;
    const int nb = b * NN;

    for (int q = t; q < NN; q += 256) {
        s2sh[q] = g_s2p[nb + q];
        u2sh[q] = g_u2[nb + q];
        v2sh[q] = g_v2[nb + q];
        invDsh[q] = g_invD[nb + q];
    }
    for (int q = t; q < 128 * 64; q += 256) {
        Msk[q >> 6][q & 63] = g_mask[(size_t)(nb + i0 + (q >> 6)) * 64 + (q & 63)];
    }

    int i_r[4];
    float s1v[4], u1v[4], v1v[4];
#pragma unroll
    for (int k = 0; k < 4; k++) {
        i_r[k] = i0 + wm * 32 + k * 8 + r;
        s1v[k] = g_s1[nb + i_r[k]];
        u1v[k] = g_u1[nb + i_r[k]];
        v1v[k] = g_v1[nb + i_r[k]];
    }

    float acc[2][8][4];
#pragma unroll
    for (int mt = 0; mt < 2; mt++)
#pragma unroll
        for (int nt = 0; nt < 8; nt++)
#pragma unroll
            for (int q = 0; q < 4; q++) acc[mt][nt][q] = 0.f;

    for (int k0 = 0; k0 < NN; k0 += 32) {
#pragma unroll
        for (int it = 0; it < 4; it++) {
            int q = t + it * 256;
            int rr = q >> 5, cc = (q & 31) * 4;
            float4 v = *(const float4*)&g_h[(size_t)(nb + k0 + rr) * FF + cc];
            float inv = invDsh[k0 + rr];
            v.x = __uint_as_float(f2tf32(v.x * inv));
            v.y = __uint_as_float(f2tf32(v.y * inv));
            v.z = __uint_as_float(f2tf32(v.z * inv));
            v.w = __uint_as_float(f2tf32(v.w * inv));
            *(float4*)&Hs[rr][cc] = v;
        }
        __syncthreads();

        const int wq = k0 >> 5;
        unsigned mw[4];
#pragma unroll
        for (int k = 0; k < 4; k++) mw[k] = Msk[wm * 32 + k * 8 + r][wq];

#pragma unroll
        for (int ks = 0; ks < 4; ks++) {
            const int jc = k0 + ks * 8 + c;
            const float s2a = s2sh[jc], u2a = u2sh[jc], v2a = v2sh[jc];
            const float s2b = s2sh[jc + 4], u2b = u2sh[jc + 4], v2b = v2sh[jc + 4];
            const int bit0 = ks * 8 + c;

            unsigned afr[2][4];
#pragma unroll
            for (int mt = 0; mt < 2; mt++) {
                unsigned wA = mw[2 * mt], wB = mw[2 * mt + 1];
                afr[mt][0] = pfrag((wA >> bit0) & 1u, s1v[2 * mt], u1v[2 * mt], v1v[2 * mt], s2a, u2a, v2a);
                afr[mt][1] = pfrag((wB >> bit0) & 1u, s1v[2 * mt + 1], u1v[2 * mt + 1], v1v[2 * mt + 1], s2a, u2a, v2a);
                afr[mt][2] = pfrag((wA >> (bit0 + 4)) & 1u, s1v[2 * mt], u1v[2 * mt], v1v[2 * mt], s2b, u2b, v2b);
                afr[mt][3] = pfrag((wB >> (bit0 + 4)) & 1u, s1v[2 * mt + 1], u1v[2 * mt + 1], v1v[2 * mt + 1], s2b, u2b, v2b);
            }
            unsigned bfr[8][2];
#pragma unroll
            for (int nt = 0; nt < 8; nt++) {
                int col = wn * 64 + nt * 8 + r;
                bfr[nt][0] = __float_as_uint(Hs[ks * 8 + c][col]);
                bfr[nt][1] = __float_as_uint(Hs[ks * 8 + c + 4][col]);
            }
#pragma unroll
            for (int mt = 0; mt < 2; mt++)
#pragma unroll
                for (int nt = 0; nt < 8; nt++) mma_tf32(acc[mt][nt], afr[mt], bfr[nt]);
        }
        __syncthreads();
    }

#pragma unroll
    for (int mt = 0; mt < 2; mt++) {
        const int rA = i_r[2 * mt], rB = i_r[2 * mt + 1];
#pragma unroll
        for (int nt = 0; nt < 8; nt++) {
            int col = wn * 64 + nt * 8 + 2 * c;
            float2 o0 = {fmaxf(acc[mt][nt][0], 0.f), fmaxf(acc[mt][nt][1], 0.f)};
            float2 o1 = {fmaxf(acc[mt][nt][2], 0.f), fmaxf(acc[mt][nt][3], 0.f)};
            *(float2*)&out[(size_t)(nb + rA) * FF + col] = o0;
            *(float2*)&out[(size_t)(nb + rB) * FF + col] = o1;
        }
    }
}

// ---------------- launch ----------------
extern "C" void kernel_launch(void* const* d_in, const int* in_sizes, int n_in,
                              void* d_out, int out_size) {
    const float* x = (const float*)d_in[0];
    const int* adj = (const int*)d_in[1];
    const float* W = (const float*)d_in[2];
    const float* bW = (const float*)d_in[3];
    const float* a1 = (const float*)d_in[4];
    const float* a2 = (const float*)d_in[5];
    const float* ba = (const float*)d_in[6];
    float* out = (float*)d_out;

    const int smem_attn = (8192 + 32 * 136) * 4 + 128 * 65 * 4;  // 83456 B
    static bool attr_set = false;
    if (!attr_set) {
        cudaFuncSetAttribute(k_attn, cudaFuncAttributeMaxDynamicSharedMemorySize, smem_attn);
        attr_set = true;
    }

    k_gemm_h<<<256, 256>>>(x, W, bW, a1, a2, ba);
    k_zeroD<<<(BATCH * NN + 255) / 256, 256>>>();
    k_pack<<<dim3(2, 32, 8), 256>>>(adj);
    k_finalizeD<<<(BATCH * NN + 255) / 256, 256>>>();
    k_attn<<<dim3(16, 8), 256, smem_attn>>>(out);
}